// round 4
// baseline (speedup 1.0000x reference)
#include <cuda_runtime.h>
#include <cstdint>
#include <cstddef>

#define B_ 4
#define S_ 2048
#define D_ 768
#define NH_ 4
#define DH_ 192
#define KC_ 4

// cluster split of the recurrence
#define CL 8            // CTAs per (b,h) cluster
#define EPB 24          // DH / CL elements per CTA
#define TPB 96          // 4 gates * EPB outputs, one thread per output
#define RSTRIDE 196     // padded row length (floats) for conflict-free LDS.128

// scratch (device globals: allocation-free)
__device__ float d_xconv[B_ * S_ * D_];                 // 25.2 MB
__device__ float d_G[S_ * B_ * NH_ * 4 * DH_];          // 100.7 MB, layout [S][B][NH][4][DH]

// ---------------------------------------------------------------------------
// 1) causal depthwise conv1d + swish
// ---------------------------------------------------------------------------
__global__ __launch_bounds__(256) void conv_swish_kernel(
    const float* __restrict__ x, const float* __restrict__ ck,
    const float* __restrict__ cb, float* __restrict__ xc)
{
    int idx = blockIdx.x * 256 + threadIdx.x;       // < B*S*D
    int d = idx % D_;
    int s = (idx / D_) & (S_ - 1);
    float acc = cb[d];
#pragma unroll
    for (int k = 0; k < KC_; k++) {
        int ss = s - (KC_ - 1) + k;
        if (ss >= 0) acc = fmaf(x[idx + (k - (KC_ - 1)) * D_], ck[k * D_ + d], acc);
    }
    xc[idx] = acc / (1.f + expf(-acc));             // swish
}

// ---------------------------------------------------------------------------
// 2) gate pre-activation GEMMs: G[s][b][h][g][e] = xin . W[g,h] + cell_bias
//    xin = xconv for g in {0(i),1(f)}, x for g in {2(z),3(o)}
//    per block: 128x64 tile of an 8192x192x192 GEMM, blockIdx.z = h*4+g
// ---------------------------------------------------------------------------
__global__ __launch_bounds__(256) void gate_gemm_kernel(
    const float* __restrict__ x, const float* __restrict__ xc,
    const float* __restrict__ Wi, const float* __restrict__ Wf,
    const float* __restrict__ Wz, const float* __restrict__ Wo,
    const float* __restrict__ cb, float* __restrict__ G)
{
    __shared__ float As[16 * 132];   // [k][m], padded
    __shared__ float Bs[16 * 68];    // [k][n], padded

    const int z = blockIdx.z;
    const int h = z >> 2;
    const int g = z & 3;
    const float* A = (g < 2 ? xc : x) + h * DH_;                 // row stride D_
    const float* W = (g == 0 ? Wi : g == 1 ? Wf : g == 2 ? Wz : Wo) + h * DH_ * DH_;
    const int m0 = blockIdx.x * 128;
    const int n0 = blockIdx.y * 64;
    const int tid = threadIdx.x;
    const int tx = tid & 15, ty = tid >> 4;

    float acc[8][4];
#pragma unroll
    for (int i = 0; i < 8; i++)
#pragma unroll
        for (int j = 0; j < 4; j++) acc[i][j] = 0.f;

    for (int k0 = 0; k0 < DH_; k0 += 16) {
        // A tile 128x16 -> As transposed
#pragma unroll
        for (int l = 0; l < 2; l++) {
            int fid = tid + l * 256;
            int r = fid >> 2, cc = fid & 3;
            float4 v = *(const float4*)(A + (size_t)(m0 + r) * D_ + k0 + cc * 4);
            As[(cc * 4 + 0) * 132 + r] = v.x;
            As[(cc * 4 + 1) * 132 + r] = v.y;
            As[(cc * 4 + 2) * 132 + r] = v.z;
            As[(cc * 4 + 3) * 132 + r] = v.w;
        }
        // B tile 16x64
        {
            int r = tid >> 4, cc = tid & 15;
            float4 v = *(const float4*)(W + (k0 + r) * DH_ + n0 + cc * 4);
            *(float4*)(Bs + r * 68 + cc * 4) = v;
        }
        __syncthreads();
#pragma unroll
        for (int k = 0; k < 16; k++) {
            float a[8], bb[4];
            *(float4*)(a)     = *(const float4*)(As + k * 132 + ty * 8);
            *(float4*)(a + 4) = *(const float4*)(As + k * 132 + ty * 8 + 4);
            *(float4*)(bb)    = *(const float4*)(Bs + k * 68 + tx * 4);
#pragma unroll
            for (int i = 0; i < 8; i++)
#pragma unroll
                for (int j = 0; j < 4; j++)
                    acc[i][j] = fmaf(a[i], bb[j], acc[i][j]);
        }
        __syncthreads();
    }

    // epilogue: scatter into [S][B][NH][4][DH] layout + cell_bias
#pragma unroll
    for (int i = 0; i < 8; i++) {
        int m = m0 + ty * 8 + i;
        int bb_ = m >> 11;            // m = b*S + s
        int s_ = m & (S_ - 1);
        float* op = G + ((size_t)(s_ * B_ + bb_) * 16 + z) * DH_ + n0 + tx * 4;
        const float* cbp = cb + g * D_ + h * DH_ + n0 + tx * 4;
#pragma unroll
        for (int j = 0; j < 4; j++) op[j] = acc[i][j] + cbp[j];
    }
}

// ---------------------------------------------------------------------------
// 3) sequential scan: 16 clusters of 8 CTAs; each cluster owns one (b,h).
//    CTA rank owns output columns [rank*24, rank*24+24) of all 4 gates.
//    R slice resident in SMEM, h replicated per CTA, exchanged via DSMEM.
// ---------------------------------------------------------------------------
__device__ __forceinline__ void st_cluster_f32(uint32_t laddr, int rank, float v) {
    uint32_t ra;
    asm volatile("mapa.shared::cluster.u32 %0, %1, %2;" : "=r"(ra) : "r"(laddr), "r"(rank));
    asm volatile("st.shared::cluster.f32 [%0], %1;" :: "r"(ra), "f"(v) : "memory");
}

__global__ void __cluster_dims__(CL, 1, 1) __launch_bounds__(TPB, 1)
scan_kernel(const float* __restrict__ G, const float* __restrict__ Rw,
            float* __restrict__ out)
{
    extern __shared__ float sm[];
    float* Rs   = sm;                      // 4*EPB*RSTRIDE floats
    float* hs   = sm + 4 * EPB * RSTRIDE;  // 2*DH_ floats (double-buffered h)
    float* pres = hs + 2 * DH_;            // TPB floats

    const int tid  = threadIdx.x;
    const int grp  = blockIdx.x >> 3;      // (b,h) group 0..15
    const int rank = blockIdx.x & (CL - 1);
    const int b = grp >> 2;
    const int h = grp & 3;

    // load R slice: Rs[(g*EPB+e)*RSTRIDE + d] = R[g][h][d][rank*EPB+e]
    for (int i = tid; i < 4 * DH_ * EPB; i += TPB) {
        int g = i / (DH_ * EPB);
        int d = (i / EPB) % DH_;
        int e = i % EPB;
        Rs[(g * EPB + e) * RSTRIDE + d] =
            Rw[((size_t)(g * NH_ + h) * DH_ + d) * DH_ + rank * EPB + e];
    }
    for (int i = tid; i < 2 * DH_; i += TPB) hs[i] = 0.f;
    __syncthreads();
    asm volatile("barrier.cluster.arrive.aligned;" ::: "memory");
    asm volatile("barrier.cluster.wait.aligned;" ::: "memory");

    const int dg = tid / EPB;              // gate 0..3
    const int de = tid % EPB;              // local e
    const float4* Rrow = (const float4*)(Rs + tid * RSTRIDE);

    // G stream for this thread's (gate, element)
    const float* Gp = G + (size_t)(b * 16 + h * 4 + dg) * DH_ + rank * EPB + de;
    float gin = Gp[0];
    const int GSTRIDE = B_ * 16 * DH_;     // 12288

    float c = 0.f, n = 0.f, mstate = 0.f;
    float* outp = nullptr;
    uint32_t hl0 = 0, hl1 = 0;
    if (tid < EPB) {
        outp = out + (size_t)b * S_ * D_ + h * DH_ + rank * EPB + tid;
        hl0 = (uint32_t)__cvta_generic_to_shared(&hs[rank * EPB + tid]);
        hl1 = (uint32_t)__cvta_generic_to_shared(&hs[DH_ + rank * EPB + tid]);
    }

#pragma unroll 1
    for (int t = 0; t < S_; ++t) {
        const float4* hv = (const float4*)(hs + (t & 1) * DH_);
        float a0 = 0.f, a1 = 0.f, a2 = 0.f, a3 = 0.f;
#pragma unroll
        for (int i = 0; i < DH_ / 4; i++) {
            float4 r = Rrow[i];
            float4 hh = hv[i];
            a0 = fmaf(r.x, hh.x, a0);
            a1 = fmaf(r.y, hh.y, a1);
            a2 = fmaf(r.z, hh.z, a2);
            a3 = fmaf(r.w, hh.w, a3);
        }
        pres[tid] = (a0 + a1) + (a2 + a3) + gin;
        __syncthreads();

        if (tid < EPB) {
            float it = pres[tid];
            float ft = pres[EPB + tid];
            float zt = pres[2 * EPB + tid];
            float ot = pres[3 * EPB + tid];
            float mn = fmaxf(ft + mstate, it);
            float ia = expf(it - mn);
            float fa = expf(ft + mstate - mn);
            c = fa * c + ia * tanhf(zt);
            n = fa * n + ia;
            mstate = mn;
            float hnew = (c / n) / (1.f + expf(-ot));
            outp[(size_t)t * D_] = hnew;
            uint32_t la = ((t + 1) & 1) ? hl1 : hl0;
#pragma unroll
            for (int r = 0; r < CL; r++) st_cluster_f32(la, r, hnew);
        }

        asm volatile("barrier.cluster.arrive.aligned;" ::: "memory");
        if (t + 1 < S_) gin = Gp[(size_t)(t + 1) * GSTRIDE];   // prefetch under barrier
        asm volatile("barrier.cluster.wait.aligned;" ::: "memory");
    }
}

// ---------------------------------------------------------------------------
// 4) in-place multi-head LayerNorm over DH per (b,s,h); warp per row
// ---------------------------------------------------------------------------
__global__ __launch_bounds__(256) void gnorm_kernel(
    float* __restrict__ out, const float* __restrict__ gs)
{
    int warp = (blockIdx.x * 256 + threadIdx.x) >> 5;  // row id, 32768 rows
    int lane = threadIdx.x & 31;
    float* base = out + (size_t)warp * DH_;
    int h = warp & (NH_ - 1);

    float v[6], s = 0.f, sq = 0.f;
#pragma unroll
    for (int j = 0; j < 6; j++) {
        v[j] = base[lane + 32 * j];
        s += v[j];
        sq += v[j] * v[j];
    }
#pragma unroll
    for (int o = 16; o > 0; o >>= 1) {
        s += __shfl_xor_sync(0xFFFFFFFFu, s, o);
        sq += __shfl_xor_sync(0xFFFFFFFFu, sq, o);
    }
    float mean = s * (1.f / DH_);
    float var = sq * (1.f / DH_) - mean * mean;
    float inv = rsqrtf(var + 1e-5f);
#pragma unroll
    for (int j = 0; j < 6; j++)
        base[lane + 32 * j] = (v[j] - mean) * inv * gs[h * DH_ + lane + 32 * j];
}

// ---------------------------------------------------------------------------
// launcher
// ---------------------------------------------------------------------------
extern "C" void kernel_launch(void* const* d_in, const int* in_sizes, int n_in,
                              void* d_out, int out_size)
{
    const float* x   = (const float*)d_in[0];
    const float* ck  = (const float*)d_in[1];
    const float* cb  = (const float*)d_in[2];
    const float* Wi  = (const float*)d_in[3];
    const float* Wf  = (const float*)d_in[4];
    const float* Wz  = (const float*)d_in[5];
    const float* Wo  = (const float*)d_in[6];
    const float* Rw  = (const float*)d_in[7];
    const float* cbias = (const float*)d_in[8];
    const float* gsc = (const float*)d_in[9];
    float* out = (float*)d_out;

    float* xconv; float* G;
    cudaGetSymbolAddress((void**)&xconv, d_xconv);
    cudaGetSymbolAddress((void**)&G, d_G);

    // 1) conv + swish
    conv_swish_kernel<<<(B_ * S_ * D_) / 256, 256>>>(x, ck, cb, xconv);

    // 2) gate GEMMs
    dim3 ggrid((B_ * S_) / 128, DH_ / 64, NH_ * 4);
    gate_gemm_kernel<<<ggrid, 256>>>(x, xconv, Wi, Wf, Wz, Wo, cbias, G);

    // 3) scan (clustered)
    const int SMEM_BYTES = (4 * EPB * RSTRIDE + 2 * DH_ + TPB) * (int)sizeof(float);
    cudaFuncSetAttribute(scan_kernel, cudaFuncAttributeMaxDynamicSharedMemorySize, SMEM_BYTES);
    scan_kernel<<<B_ * NH_ * CL, TPB, SMEM_BYTES>>>(G, Rw, out);

    // 4) per-head layernorm in-place
    gnorm_kernel<<<(B_ * S_ * NH_) / 8, 256>>>(out, gsc);
}